// round 1
// baseline (speedup 1.0000x reference)
#include <cuda_runtime.h>
#include <math.h>

// Problem constants
#define S_   256
#define B_   2
#define HID_ 512
#define NH_  8
#define HD_  64
// flat chunk count per batch: S_*HID_/HD_ = 2048
#define NCH_ 2048

// ---------------- scratch (__device__ globals; no allocation allowed) --------
__device__ float g_mx  [3 * B_ * S_ * HID_];   // mobius matvec raw results
__device__ float g_lin [3 * B_ * S_ * HID_];   // ql/kl/vl (post logmap0/chunk-expmap0)
__device__ float g_qn2 [B_ * NCH_];            // ||ql chunk||^2
__device__ float g_kl2 [B_ * NCH_];            // ||kl chunk||^2
__device__ float g_gamma[B_ * NCH_];           // 2/max(1-||vl||^2,eps)
__device__ float g_probs[B_ * NH_ * S_ * S_];  // sigmoid scores
__device__ float g_ctx [B_ * NH_ * S_ * HD_];  // midpoint result [b,h,q,d]

// ---------------- helpers ----------------------------------------------------
__device__ __forceinline__ float artanh_pos(float x) {
    // matches jnp.arctanh(clip(x, -1+1e-7, 1-1e-7)) for x >= 0
    x = fminf(x, 1.f - 1e-7f);
    return 0.5f * logf((1.f + x) / (1.f - x));
}

__device__ __forceinline__ float warp_sum(float v) {
#pragma unroll
    for (int o = 16; o; o >>= 1) v += __shfl_xor_sync(0xffffffffu, v, o);
    return v;
}

// block of 256 threads, sh must hold 8 floats
__device__ __forceinline__ float block_sum256(float v, float* sh) {
    v = warp_sum(v);
    int w = threadIdx.x >> 5;
    if ((threadIdx.x & 31) == 0) sh[w] = v;
    __syncthreads();
    float t = 0.f;
#pragma unroll
    for (int i = 0; i < 8; i++) t += sh[i];
    __syncthreads();
    return t;
}

// ---------------- K1: MX = X @ W^T for Wq,Wk,Wv -------------------------------
// X[r, j] = query[s, b, j], r = b*256 + s.  C cols 0..1535 map to (m, i).
// Output g_mx layout [m][b][s][i].
__global__ __launch_bounds__(256) void gemm_kernel(
    const float* __restrict__ qin, const float* __restrict__ Wq,
    const float* __restrict__ Wk,  const float* __restrict__ Wv)
{
    __shared__ __align__(16) float Xs[16][64];
    __shared__ __align__(16) float Ws[16][64];

    int bx = blockIdx.x;  // 0..23 col tile
    int by = blockIdx.y;  // 0..7  row tile
    int t  = threadIdx.x;
    int tx = t & 15, ty = t >> 4;

    int m = bx >> 3;
    const float* W = (m == 0) ? Wq : (m == 1) ? Wk : Wv;
    int ibase = (bx & 7) * 64;

    int lr = t >> 2;           // 0..63
    int lk = (t & 3) * 4;      // 0,4,8,12

    int grow = by * 64 + lr;
    int gb = grow >> 8, gs = grow & 255;
    const float* xptr = qin + (gs * 2 + gb) * 512 + lk;
    const float* wptr = W + (ibase + lr) * 512 + lk;

    float acc[4][4] = {};

    for (int k0 = 0; k0 < 512; k0 += 16) {
        float4 xv = *(const float4*)(xptr + k0);
        float4 wv = *(const float4*)(wptr + k0);
        Xs[lk + 0][lr] = xv.x; Xs[lk + 1][lr] = xv.y;
        Xs[lk + 2][lr] = xv.z; Xs[lk + 3][lr] = xv.w;
        Ws[lk + 0][lr] = wv.x; Ws[lk + 1][lr] = wv.y;
        Ws[lk + 2][lr] = wv.z; Ws[lk + 3][lr] = wv.w;
        __syncthreads();
#pragma unroll
        for (int kk = 0; kk < 16; kk++) {
            float4 a = *(const float4*)&Xs[kk][ty * 4];
            float4 b = *(const float4*)&Ws[kk][tx * 4];
            acc[0][0] += a.x * b.x; acc[0][1] += a.x * b.y; acc[0][2] += a.x * b.z; acc[0][3] += a.x * b.w;
            acc[1][0] += a.y * b.x; acc[1][1] += a.y * b.y; acc[1][2] += a.y * b.z; acc[1][3] += a.y * b.w;
            acc[2][0] += a.z * b.x; acc[2][1] += a.z * b.y; acc[2][2] += a.z * b.z; acc[2][3] += a.z * b.w;
            acc[3][0] += a.w * b.x; acc[3][1] += a.w * b.y; acc[3][2] += a.w * b.z; acc[3][3] += a.w * b.w;
        }
        __syncthreads();
    }

    int row0 = by * 64 + ty * 4;
    int col0 = ibase + tx * 4;
#pragma unroll
    for (int i = 0; i < 4; i++) {
        int row = row0 + i;
        int b = row >> 8, s = row & 255;
        float4 v = make_float4(acc[i][0], acc[i][1], acc[i][2], acc[i][3]);
        *(float4*)&g_mx[(((m * 2 + b) * 256 + s) * 512) + col0] = v;
    }
}

// ---------------- K2: per-row manifold linear + logmap0 + chunk expmap0 ------
// grid (512, 3), 256 threads; thread t owns elems 2t, 2t+1.
__global__ __launch_bounds__(256) void postproc_kernel(
    const float* __restrict__ qin, const float* __restrict__ bq,
    const float* __restrict__ bk,  const float* __restrict__ bv)
{
    __shared__ float red[8];
    int r = blockIdx.x;            // 0..511
    int m = blockIdx.y;            // 0..2
    int b = r >> 8, s = r & 255;
    int t = threadIdx.x;
    int i0 = 2 * t, i1 = 2 * t + 1;

    const float* xrow  = qin + (s * 2 + b) * 512;
    const float* mxrow = g_mx + ((m * 2 + b) * 256 + s) * 512;
    const float* bias  = (m == 0) ? bq : (m == 1) ? bk : bv;

    float x0 = xrow[i0],  x1 = xrow[i1];
    float mx0 = mxrow[i0], mx1 = mxrow[i1];

    float sx  = block_sum256(x0 * x0 + x1 * x1, red);
    float smx = block_sum256(mx0 * mx0 + mx1 * mx1, red);

    float xn  = fmaxf(sqrtf(sx),  1e-15f);
    float mxn = fmaxf(sqrtf(smx), 1e-15f);
    float arg = (mxn / xn) * artanh_pos(xn);
    float scm = tanhf(arg) / mxn;          // mobius_matvec scale
    float r0 = scm * mx0, r1 = scm * mx1;

    float b0 = bias[i0], b1 = bias[i1];
    float xy = block_sum256(r0 * b0 + r1 * b1, red);
    float x2 = block_sum256(r0 * r0 + r1 * r1, red);
    float y2 = block_sum256(b0 * b0 + b1 * b1, red);

    float ca = 1.f + 2.f * xy + y2;
    float cb = 1.f - x2;
    float den = fmaxf(1.f + 2.f * xy + x2 * y2, 1e-15f);
    float o0 = (ca * r0 + cb * b0) / den;
    float o1 = (ca * r1 + cb * b1) / den;

    float so = block_sum256(o0 * o0 + o1 * o1, red);
    float n = fmaxf(sqrtf(so), 1e-15f);
    if (n > 0.996f) {                      // projx, maxnorm = (1-4e-3)/sqrt(c)
        float f = 0.996f / n;
        o0 *= f; o1 *= f; n = 0.996f;
    }

    // logmap0 over HID
    float ls = artanh_pos(n) / n;
    float u0 = ls * o0, u1 = ls * o1;

    // per-64-chunk expmap0: warp w == chunk w (elems 2t,2t+1 stay in-chunk)
    float cu = warp_sum(u0 * u0 + u1 * u1);
    float cn = fmaxf(sqrtf(cu), 1e-15f);
    float es = tanhf(cn) / cn;
    float l0 = es * u0, l1 = es * u1;

    float* Lrow = g_lin + ((m * 2 + b) * 256 + s) * 512;
    Lrow[i0] = l0; Lrow[i1] = l1;

    if ((t & 31) == 0) {
        int w = t >> 5;
        float st = es * es * cu;           // squared norm after expmap0
        int idx = b * NCH_ + s * 8 + w;    // flat chunk index == (h*256+s2)
        if (m == 0)       g_qn2[idx] = st;
        else if (m == 1)  g_kl2[idx] = st;
        else              g_gamma[idx] = 2.f / fmaxf(1.f - st, 1e-15f);
    }
}

// ---------------- K3: pairwise hyperbolic distance scores + sigmoid ----------
// grid (16 qtiles, 16 bh), 256 threads; thread handles n = tid for 16 q's.
#define SMEM3 ((256 * 65 + 16 * 64 + 16 + 256) * 4)
__global__ __launch_bounds__(256) void scores_kernel()
{
    extern __shared__ float sm[];
    float* kls = sm;                 // [256][65] padded
    float* qs  = sm + 256 * 65;      // [16][64]
    float* q2s = qs + 1024;          // [16]
    float* k2s = q2s + 16;           // [256]

    int qt = blockIdx.x, bh = blockIdx.y;
    int base = bh * 256;             // flat chunk base = b*2048 + h*256
    int t = threadIdx.x;
    const float* gql = g_lin;
    const float* gkl = g_lin + B_ * S_ * HID_;

    for (int idx = t; idx < 256 * 64; idx += 256) {
        int n = idx >> 6, d = idx & 63;
        kls[n * 65 + d] = gkl[base * 64 + idx];
    }
    int qg0 = qt * 16;
    for (int idx = t; idx < 1024; idx += 256)
        qs[idx] = gql[(base + qg0) * 64 + idx];
    if (t < 16) q2s[t] = g_qn2[base + qg0 + t];
    k2s[t] = g_kl2[base + t];
    __syncthreads();

    int n = t;
    float y2 = k2s[n];
    const float* kr = &kls[n * 65];
    float* prow = g_probs + (bh * 256 + qg0) * 256 + n;

    for (int qq = 0; qq < 16; qq++) {
        const float* qr = &qs[qq * 64];
        float x2 = q2s[qq];
        float xy = 0.f;
#pragma unroll
        for (int d = 0; d < 64; d++) xy += qr[d] * kr[d];

        // mobius_add(-ql, kl)
        float A  = 1.f - 2.f * xy + y2;
        float Bc = 1.f - x2;
        float den = fmaxf(1.f - 2.f * xy + x2 * y2, 1e-15f);
        float den2 = den * den;
        float tacc = 0.f;
#pragma unroll
        for (int d = 0; d < 64; d++) {
            float num = Bc * kr[d] - A * qr[d];
            // min(den^2/num^2, 1e30) == max(diff^2,1e-30)^-1 semantics
            tacc += fminf(__fdividef(den2, num * num), 1e30f);
        }
        float t1 = rsqrtf(tacc);
        float sc = -2.f * artanh_pos(t1);
        sc = fminf(fmaxf(sc, -1e10f), 1e10f);
        float p = 1.f / (1.f + expf(-sc));
        prow[qq * 256] = p;
    }
}

// ---------------- K4: gyro-midpoint einsums + mobius_scalar_mul(0.5) ---------
#define SMEM4 ((256 * 68 + 16 * 256 + 256 + 16 * 68 + 16) * 4)
__global__ __launch_bounds__(256) void midpoint_kernel()
{
    extern __shared__ float sm[];
    float* gvs  = sm;                       // [256][68] gamma*vl, padded/aligned
    float* ps   = gvs + 256 * 68;           // [16][256] probs
    float* gm1  = ps + 16 * 256;            // [256] gamma-1
    float* noms = gm1 + 256;                // [16][68]
    float* dns  = noms + 16 * 68;           // [16]

    int qt = blockIdx.x, bh = blockIdx.y, t = threadIdx.x;
    int base = bh * 256;
    const float* gvl = g_lin + 2 * B_ * S_ * HID_;

    for (int idx = t; idx < 256 * 64; idx += 256) {
        int n = idx >> 6, d = idx & 63;
        gvs[n * 68 + d] = g_gamma[base + n] * gvl[base * 64 + idx];
    }
    gm1[t] = g_gamma[base + t] - 1.f;
    int qg0 = qt * 16;
    for (int idx = t; idx < 16 * 256; idx += 256)
        ps[idx] = g_probs[(bh * 256 + qg0) * 256 + idx];
    __syncthreads();

    int qq = t >> 4, dg = (t & 15) * 4;
    float a0 = 0.f, a1 = 0.f, a2 = 0.f, a3 = 0.f, dn = 0.f;
    const float* pr = &ps[qq * 256];
#pragma unroll 8
    for (int nn = 0; nn < 256; nn++) {
        float pv = pr[nn];
        float4 g4 = *(const float4*)&gvs[nn * 68 + dg];
        a0 += pv * g4.x; a1 += pv * g4.y; a2 += pv * g4.z; a3 += pv * g4.w;
        dn += pv * gm1[nn];
    }
    noms[qq * 68 + dg + 0] = a0; noms[qq * 68 + dg + 1] = a1;
    noms[qq * 68 + dg + 2] = a2; noms[qq * 68 + dg + 3] = a3;
    if (dg == 0) dns[qq] = dn;
    __syncthreads();

    int w = t >> 5, l = t & 31;
    for (int qi = w; qi < 16; qi += 8) {
        float dd = dns[qi];
        float sg = (dd >= 0.f) ? 1.f : -1.f;
        dd = sg * fmaxf(fabsf(dd), 1e-10f);
        float y0 = noms[qi * 68 + l] / dd;
        float y1 = noms[qi * 68 + 32 + l] / dd;
        float nn = warp_sum(y0 * y0 + y1 * y1);
        float nm = fmaxf(sqrtf(nn), 1e-15f);
        float scale = tanhf(0.5f * artanh_pos(nm)) / nm;   // mobius_scalar_mul(0.5)
        float* crow = g_ctx + (bh * 256 + qg0 + qi) * 64;
        crow[l]      = scale * y0;
        crow[l + 32] = scale * y1;
    }
}

// ---------------- K5: head-chunk logmap0 -> 512 expmap0 -> [S,B,HID] out -----
// grid (256 q, 2 b), 256 threads; warp w = head h.
__global__ __launch_bounds__(256) void finalize_kernel(float* __restrict__ out)
{
    __shared__ float sh[8];
    int q = blockIdx.x, b = blockIdx.y;
    int t = threadIdx.x, w = t >> 5, l = t & 31;

    const float* crow = g_ctx + ((b * 8 + w) * 256 + q) * 64;
    float c0 = crow[l], c1 = crow[l + 32];

    float cu = warp_sum(c0 * c0 + c1 * c1);
    float cn = fmaxf(sqrtf(cu), 1e-15f);
    float ls = artanh_pos(cn) / cn;        // logmap0 over HD
    float u0 = ls * c0, u1 = ls * c1;

    float us = warp_sum(u0 * u0 + u1 * u1);
    if (l == 0) sh[w] = us;
    __syncthreads();
    float tot = 0.f;
#pragma unroll
    for (int i = 0; i < 8; i++) tot += sh[i];
    float tn = fmaxf(sqrtf(tot), 1e-15f);
    float fs = tanhf(tn) / tn;             // expmap0 over HID

    float* orow = out + (q * 2 + b) * 512 + w * 64;
    orow[l]      = fs * u0;
    orow[l + 32] = fs * u1;
}

__global__ __launch_bounds__(256) void copy_probs_kernel(float* __restrict__ dst)
{
    int i = blockIdx.x * 256 + threadIdx.x;
    dst[i] = g_probs[i];
}

// ---------------- launch ------------------------------------------------------
extern "C" void kernel_launch(void* const* d_in, const int* in_sizes, int n_in,
                              void* d_out, int out_size)
{
    const float* qin = (const float*)d_in[0];
    const float* Wq  = (const float*)d_in[1];
    const float* bq  = (const float*)d_in[2];
    const float* Wk  = (const float*)d_in[3];
    const float* bk  = (const float*)d_in[4];
    const float* Wv  = (const float*)d_in[5];
    const float* bv  = (const float*)d_in[6];
    float* out = (float*)d_out;

    cudaFuncSetAttribute(scores_kernel,   cudaFuncAttributeMaxDynamicSharedMemorySize, SMEM3);
    cudaFuncSetAttribute(midpoint_kernel, cudaFuncAttributeMaxDynamicSharedMemorySize, SMEM4);

    gemm_kernel<<<dim3(24, 8), 256>>>(qin, Wq, Wk, Wv);
    postproc_kernel<<<dim3(512, 3), 256>>>(qin, bq, bk, bv);
    scores_kernel<<<dim3(16, 16), 256, SMEM3>>>();
    midpoint_kernel<<<dim3(16, 16), 256, SMEM4>>>();
    finalize_kernel<<<dim3(256, 2), 256>>>(out);

    const int ctx_elems = S_ * B_ * HID_;                 // 262144
    const int prob_elems = B_ * NH_ * S_ * S_;            // 1048576
    if (out_size >= ctx_elems + prob_elems) {
        copy_probs_kernel<<<prob_elems / 256, 256>>>(out + ctx_elems);
    }
}

// round 2
// speedup vs baseline: 1.0498x; 1.0498x over previous
#include <cuda_runtime.h>
#include <math.h>

typedef unsigned long long ull;

// Problem constants
#define S_   256
#define B_   2
#define HID_ 512
#define NH_  8
#define HD_  64
#define NCH_ 2048

// ---------------- scratch ----------------------------------------------------
__device__ float g_mx  [3 * B_ * S_ * HID_];
__device__ float g_lin [3 * B_ * S_ * HID_];
__device__ float g_qn2 [B_ * NCH_];
__device__ float g_kl2 [B_ * NCH_];
__device__ float g_gamma[B_ * NCH_];
__device__ float g_probs[B_ * NH_ * S_ * S_];  // fallback if out has no room
__device__ float g_ctx [B_ * NH_ * S_ * HD_];

// ---------------- f32x2 packed helpers ---------------------------------------
#define FMA2(d, a, b, c) \
    asm("fma.rn.f32x2 %0, %1, %2, %3;" : "=l"(d) : "l"(a), "l"(b), "l"(c))
#define MUL2(d, a, b) \
    asm("mul.rn.f32x2 %0, %1, %2;" : "=l"(d) : "l"(a), "l"(b))
#define PK2(d, lo, hi) \
    asm("mov.b64 %0, {%1, %2};" : "=l"(d) : "f"(lo), "f"(hi))
#define UPK2(lo, hi, s) \
    asm("mov.b64 {%0, %1}, %2;" : "=f"(lo), "=f"(hi) : "l"(s))

__device__ __forceinline__ float frcp(float x) {
    float r; asm("rcp.approx.f32 %0, %1;" : "=f"(r) : "f"(x)); return r;
}

__device__ __forceinline__ float artanh_pos(float x) {
    x = fminf(x, 1.f - 1e-7f);
    return 0.5f * __logf((1.f + x) / (1.f - x));
}

__device__ __forceinline__ float warp_sum(float v) {
#pragma unroll
    for (int o = 16; o; o >>= 1) v += __shfl_xor_sync(0xffffffffu, v, o);
    return v;
}

// batched block reductions (256 threads), red must hold 8*N floats
template<int N>
__device__ __forceinline__ void bsum(float (&v)[N], float* red) {
#pragma unroll
    for (int i = 0; i < N; i++) v[i] = warp_sum(v[i]);
    int w = threadIdx.x >> 5;
    if ((threadIdx.x & 31) == 0) {
#pragma unroll
        for (int i = 0; i < N; i++) red[i * 8 + w] = v[i];
    }
    __syncthreads();
#pragma unroll
    for (int i = 0; i < N; i++) {
        float s = 0.f;
#pragma unroll
        for (int j = 0; j < 8; j++) s += red[i * 8 + j];
        v[i] = s;
    }
    __syncthreads();
}

// ---------------- K1: MX = X @ W^T (f32x2) ------------------------------------
__global__ __launch_bounds__(256) void gemm_kernel(
    const float* __restrict__ qin, const float* __restrict__ Wq,
    const float* __restrict__ Wk,  const float* __restrict__ Wv)
{
    __shared__ __align__(16) float Xs[16][64];
    __shared__ __align__(16) float Ws[16][64];

    int bx = blockIdx.x, by = blockIdx.y;
    int t  = threadIdx.x;
    int tx = t & 15, ty = t >> 4;

    int m = bx >> 3;
    const float* W = (m == 0) ? Wq : (m == 1) ? Wk : Wv;
    int ibase = (bx & 7) * 64;

    int lr = t >> 2;
    int lk = (t & 3) * 4;

    int grow = by * 64 + lr;
    int gb = grow >> 8, gs = grow & 255;
    const float* xptr = qin + (gs * 2 + gb) * 512 + lk;
    const float* wptr = W + (ibase + lr) * 512 + lk;

    ull acc2[4][2];
#pragma unroll
    for (int i = 0; i < 4; i++) { acc2[i][0] = 0ull; acc2[i][1] = 0ull; }

    for (int k0 = 0; k0 < 512; k0 += 16) {
        float4 xv = *(const float4*)(xptr + k0);
        float4 wv = *(const float4*)(wptr + k0);
        Xs[lk + 0][lr] = xv.x; Xs[lk + 1][lr] = xv.y;
        Xs[lk + 2][lr] = xv.z; Xs[lk + 3][lr] = xv.w;
        Ws[lk + 0][lr] = wv.x; Ws[lk + 1][lr] = wv.y;
        Ws[lk + 2][lr] = wv.z; Ws[lk + 3][lr] = wv.w;
        __syncthreads();
#pragma unroll
        for (int kk = 0; kk < 16; kk++) {
            float4 a = *(const float4*)&Xs[kk][ty * 4];
            float4 b = *(const float4*)&Ws[kk][tx * 4];
            ull b01, b23; PK2(b01, b.x, b.y); PK2(b23, b.z, b.w);
            ull aii;
            PK2(aii, a.x, a.x);
            FMA2(acc2[0][0], aii, b01, acc2[0][0]); FMA2(acc2[0][1], aii, b23, acc2[0][1]);
            PK2(aii, a.y, a.y);
            FMA2(acc2[1][0], aii, b01, acc2[1][0]); FMA2(acc2[1][1], aii, b23, acc2[1][1]);
            PK2(aii, a.z, a.z);
            FMA2(acc2[2][0], aii, b01, acc2[2][0]); FMA2(acc2[2][1], aii, b23, acc2[2][1]);
            PK2(aii, a.w, a.w);
            FMA2(acc2[3][0], aii, b01, acc2[3][0]); FMA2(acc2[3][1], aii, b23, acc2[3][1]);
        }
        __syncthreads();
    }

    int row0 = by * 64 + ty * 4;
    int col0 = ibase + tx * 4;
#pragma unroll
    for (int i = 0; i < 4; i++) {
        int row = row0 + i;
        int b = row >> 8, s = row & 255;
        float4 v;
        UPK2(v.x, v.y, acc2[i][0]);
        UPK2(v.z, v.w, acc2[i][1]);
        *(float4*)&g_mx[(((m * 2 + b) * 256 + s) * 512) + col0] = v;
    }
}

// ---------------- K2: manifold linear + logmap0 + chunk expmap0 ---------------
__global__ __launch_bounds__(256) void postproc_kernel(
    const float* __restrict__ qin, const float* __restrict__ bq,
    const float* __restrict__ bk,  const float* __restrict__ bv)
{
    __shared__ float red[24];
    int r = blockIdx.x;
    int m = blockIdx.y;
    int b = r >> 8, s = r & 255;
    int t = threadIdx.x;
    int i0 = 2 * t, i1 = 2 * t + 1;

    const float* xrow  = qin + (s * 2 + b) * 512;
    const float* mxrow = g_mx + ((m * 2 + b) * 256 + s) * 512;
    const float* bias  = (m == 0) ? bq : (m == 1) ? bk : bv;

    float x0 = xrow[i0],  x1 = xrow[i1];
    float mx0 = mxrow[i0], mx1 = mxrow[i1];

    float v2[2] = { x0 * x0 + x1 * x1, mx0 * mx0 + mx1 * mx1 };
    bsum<2>(v2, red);

    float xn  = fmaxf(sqrtf(v2[0]), 1e-15f);
    float mxn = fmaxf(sqrtf(v2[1]), 1e-15f);
    float arg = (mxn / xn) * artanh_pos(xn);
    float scm = tanhf(arg) / mxn;
    float r0 = scm * mx0, r1 = scm * mx1;

    float b0 = bias[i0], b1 = bias[i1];
    float v3[3] = { r0 * b0 + r1 * b1, r0 * r0 + r1 * r1, b0 * b0 + b1 * b1 };
    bsum<3>(v3, red);
    float xy = v3[0], x2 = v3[1], y2 = v3[2];

    float ca = 1.f + 2.f * xy + y2;
    float cb = 1.f - x2;
    float den = fmaxf(1.f + 2.f * xy + x2 * y2, 1e-15f);
    float o0 = (ca * r0 + cb * b0) / den;
    float o1 = (ca * r1 + cb * b1) / den;

    float v1[1] = { o0 * o0 + o1 * o1 };
    bsum<1>(v1, red);
    float n = fmaxf(sqrtf(v1[0]), 1e-15f);
    if (n > 0.996f) {
        float f = 0.996f / n;
        o0 *= f; o1 *= f; n = 0.996f;
    }

    float ls = artanh_pos(n) / n;       // logmap0 over HID
    float u0 = ls * o0, u1 = ls * o1;

    float cu = warp_sum(u0 * u0 + u1 * u1);   // per-64 chunk
    float cn = fmaxf(sqrtf(cu), 1e-15f);
    float es = tanhf(cn) / cn;
    float l0 = es * u0, l1 = es * u1;

    float* Lrow = g_lin + ((m * 2 + b) * 256 + s) * 512;
    Lrow[i0] = l0; Lrow[i1] = l1;

    if ((t & 31) == 0) {
        int w = t >> 5;
        float st = es * es * cu;
        int idx = b * NCH_ + s * 8 + w;
        if (m == 0)       g_qn2[idx] = st;
        else if (m == 1)  g_kl2[idx] = st;
        else              g_gamma[idx] = 2.f / fmaxf(1.f - st, 1e-15f);
    }
}

// ---------------- K3: pairwise scores + sigmoid -------------------------------
// grid (32 qtiles of 8, 16 bh), 256 threads; thread = n, K-row in registers.
__global__ __launch_bounds__(256) void scores_kernel(float* __restrict__ pp)
{
    __shared__ float qs[8 * 64];
    __shared__ float q2s[8];

    int qt = blockIdx.x, bh = blockIdx.y;
    int base = bh * 256;
    int qg0 = qt * 8;
    int t = threadIdx.x;

    const float* gql = g_lin;
    const float* gkl = g_lin + B_ * S_ * HID_;

    // stage q tile
    for (int idx = t; idx < 8 * 64; idx += 256)
        qs[idx] = gql[(base + qg0) * 64 + idx];
    if (t < 8) q2s[t] = g_qn2[base + qg0 + t];

    // K row of this n into registers (32 packed f32x2)
    ull kr2[32];
    {
        const float* krow = gkl + (base + t) * 64;
#pragma unroll
        for (int i = 0; i < 16; i++) {
            float4 v = *(const float4*)(krow + i * 4);
            PK2(kr2[2 * i],     v.x, v.y);
            PK2(kr2[2 * i + 1], v.z, v.w);
        }
    }
    float y2 = g_kl2[base + t];
    __syncthreads();

    float* prow = pp + (size_t)(bh * 256 + qg0) * 256 + t;

    for (int q = 0; q < 8; q++) {
        const float* qrow = &qs[q * 64];
        float x2 = q2s[q];

        // dot(q, k) — 4 packed accumulators
        ull a0 = 0ull, a1 = 0ull, a2 = 0ull, a3 = 0ull;
#pragma unroll
        for (int i = 0; i < 32; i += 4) {
            ull qv0 = *(const ull*)(qrow + 2 * i);
            ull qv1 = *(const ull*)(qrow + 2 * i + 2);
            ull qv2 = *(const ull*)(qrow + 2 * i + 4);
            ull qv3 = *(const ull*)(qrow + 2 * i + 6);
            FMA2(a0, kr2[i],     qv0, a0);
            FMA2(a1, kr2[i + 1], qv1, a1);
            FMA2(a2, kr2[i + 2], qv2, a2);
            FMA2(a3, kr2[i + 3], qv3, a3);
        }
        float s0, s1, s2, s3, s4, s5, s6, s7;
        UPK2(s0, s1, a0); UPK2(s2, s3, a1); UPK2(s4, s5, a2); UPK2(s6, s7, a3);
        float xy = ((s0 + s1) + (s2 + s3)) + ((s4 + s5) + (s6 + s7));

        float A  = 1.f - 2.f * xy + y2;
        float Bc = 1.f - x2;
        float den = fmaxf(1.f - 2.f * xy + x2 * y2, 1e-15f);
        float den2 = den * den;
        float cap = __fdividef(1e30f, den2);

        ull nA2, B2;
        PK2(nA2, -A, -A);
        PK2(B2, Bc, Bc);

        float t0 = 0.f, t1a = 0.f;
#pragma unroll
        for (int i = 0; i < 32; i++) {
            ull qv = *(const ull*)(qrow + 2 * i);
            ull u; MUL2(u, B2, kr2[i]);
            ull num; FMA2(num, nA2, qv, u);
            ull sq; MUL2(sq, num, num);
            float q0, q1; UPK2(q0, q1, sq);
            t0  += fminf(frcp(q0), cap);
            t1a += fminf(frcp(q1), cap);
        }
        float tacc = (t0 + t1a) * den2;
        float tt = rsqrtf(tacc);
        float sc = -2.f * artanh_pos(tt);
        sc = fminf(fmaxf(sc, -1e10f), 1e10f);
        float p = __fdividef(1.f, 1.f + __expf(-sc));
        prow[q * 256] = p;
    }
}

// ---------------- K4: gyro-midpoint + mobius_scalar_mul(0.5) ------------------
// grid (16 qtiles of 16, 16 bh), 512 threads: warp = q, lane owns d-pair.
#define SMEM4 (256 * 68 * 4)
__global__ __launch_bounds__(512) void midpoint_kernel(const float* __restrict__ pp)
{
    extern __shared__ float sm[];
    float* gvs = sm;                         // [256][68]: 0..63 gamma*vl, 64 gamma-1

    int qt = blockIdx.x, bh = blockIdx.y, t = threadIdx.x;
    int base = bh * 256;
    int qg0 = qt * 16;
    const float* gvl = g_lin + 2 * B_ * S_ * HID_;

    // stage gamma*vl (float4), gamma-1 in col 64
    for (int idx4 = t; idx4 < 4096; idx4 += 512) {
        int n = idx4 >> 4, dq = (idx4 & 15) * 4;
        float g = g_gamma[base + n];
        float4 v = *(const float4*)&gvl[(base + n) * 64 + dq];
        v.x *= g; v.y *= g; v.z *= g; v.w *= g;
        *(float4*)&gvs[n * 68 + dq] = v;
    }
    if (t < 256) gvs[t * 68 + 64] = g_gamma[base + t] - 1.f;
    __syncthreads();

    int q = t >> 5, l = t & 31;              // warp q, lane l -> d = 2l, 2l+1
    const float* prow = pp + (size_t)(bh * 256 + qg0 + q) * 256;

    ull acc = 0ull;
    float dn = 0.f;
#pragma unroll 8
    for (int nn = 0; nn < 256; nn++) {
        float pv = prow[nn];                 // warp-broadcast LDG (L1/L2)
        ull pv2; PK2(pv2, pv, pv);
        ull gv = *(const ull*)&gvs[nn * 68 + 2 * l];
        FMA2(acc, pv2, gv, acc);
        dn = fmaf(pv, gvs[nn * 68 + 64], dn);
    }

    float sg = (dn >= 0.f) ? 1.f : -1.f;
    float dd = sg * fmaxf(fabsf(dn), 1e-10f);
    float y0, y1; UPK2(y0, y1, acc);
    y0 = __fdividef(y0, dd);
    y1 = __fdividef(y1, dd);
    float nn2 = warp_sum(y0 * y0 + y1 * y1);
    float nm = fmaxf(sqrtf(nn2), 1e-15f);
    float scale = tanhf(0.5f * artanh_pos(nm)) / nm;
    float* crow = g_ctx + (size_t)(bh * 256 + qg0 + q) * 64;
    crow[2 * l]     = scale * y0;
    crow[2 * l + 1] = scale * y1;
}

// ---------------- K5: head logmap0 -> 512 expmap0 -> [S,B,HID] out ------------
__global__ __launch_bounds__(256) void finalize_kernel(float* __restrict__ out)
{
    __shared__ float sh[8];
    int q = blockIdx.x, b = blockIdx.y;
    int t = threadIdx.x, w = t >> 5, l = t & 31;

    const float* crow = g_ctx + ((b * 8 + w) * 256 + q) * 64;
    float c0 = crow[l], c1 = crow[l + 32];

    float cu = warp_sum(c0 * c0 + c1 * c1);
    float cn = fmaxf(sqrtf(cu), 1e-15f);
    float ls = artanh_pos(cn) / cn;
    float u0 = ls * c0, u1 = ls * c1;

    float us = warp_sum(u0 * u0 + u1 * u1);
    if (l == 0) sh[w] = us;
    __syncthreads();
    float tot = 0.f;
#pragma unroll
    for (int i = 0; i < 8; i++) tot += sh[i];
    float tn = fmaxf(sqrtf(tot), 1e-15f);
    float fs = tanhf(tn) / tn;

    float* orow = out + (q * 2 + b) * 512 + w * 64;
    orow[l]      = fs * u0;
    orow[l + 32] = fs * u1;
}

// ---------------- launch ------------------------------------------------------
extern "C" void kernel_launch(void* const* d_in, const int* in_sizes, int n_in,
                              void* d_out, int out_size)
{
    const float* qin = (const float*)d_in[0];
    const float* Wq  = (const float*)d_in[1];
    const float* bq  = (const float*)d_in[2];
    const float* Wk  = (const float*)d_in[3];
    const float* bk  = (const float*)d_in[4];
    const float* Wv  = (const float*)d_in[5];
    const float* bv  = (const float*)d_in[6];
    float* out = (float*)d_out;

    const int ctx_elems  = S_ * B_ * HID_;        // 262144
    const int prob_elems = B_ * NH_ * S_ * S_;    // 1048576

    float* pp;
    if (out_size >= ctx_elems + prob_elems) {
        pp = out + ctx_elems;                     // write probs straight to out
    } else {
        void* sym = nullptr;
        cudaGetSymbolAddress(&sym, g_probs);
        pp = (float*)sym;
    }

    cudaFuncSetAttribute(midpoint_kernel, cudaFuncAttributeMaxDynamicSharedMemorySize, SMEM4);

    gemm_kernel<<<dim3(24, 8), 256>>>(qin, Wq, Wk, Wv);
    postproc_kernel<<<dim3(512, 3), 256>>>(qin, bq, bk, bv);
    scores_kernel<<<dim3(32, 16), 256>>>(pp);
    midpoint_kernel<<<dim3(16, 16), 512, SMEM4>>>(pp);
    finalize_kernel<<<dim3(256, 2), 256>>>(out);
}

// round 4
// speedup vs baseline: 1.3677x; 1.3028x over previous
#include <cuda_runtime.h>
#include <math.h>

typedef unsigned long long ull;

// Problem constants
#define S_   256
#define B_   2
#define HID_ 512
#define NH_  8
#define HD_  64
#define NCH_ 2048

// ---------------- scratch ----------------------------------------------------
__device__ float g_mx  [2][3 * B_ * S_ * HID_];  // K-split partials
__device__ float g_lin [3 * B_ * S_ * HID_];
__device__ float g_qn2 [B_ * NCH_];
__device__ float g_kl2 [B_ * NCH_];
__device__ float g_gamma[B_ * NCH_];
__device__ float g_probs[B_ * NH_ * S_ * S_];    // fallback if out has no room
__device__ float g_ctx [B_ * NH_ * S_ * HD_];

// ---------------- f32x2 packed helpers ---------------------------------------
#define FMA2(d, a, b, c) \
    asm("fma.rn.f32x2 %0, %1, %2, %3;" : "=l"(d) : "l"(a), "l"(b), "l"(c))
#define MUL2(d, a, b) \
    asm("mul.rn.f32x2 %0, %1, %2;" : "=l"(d) : "l"(a), "l"(b))
#define PK2(d, lo, hi) \
    asm("mov.b64 %0, {%1, %2};" : "=l"(d) : "f"(lo), "f"(hi))
#define UPK2(lo, hi, s) \
    asm("mov.b64 {%0, %1}, %2;" : "=f"(lo), "=f"(hi) : "l"(s))

__device__ __forceinline__ float frcp(float x) {
    float r; asm("rcp.approx.f32 %0, %1;" : "=f"(r) : "f"(x)); return r;
}

__device__ __forceinline__ float artanh_pos(float x) {
    x = fminf(x, 1.f - 1e-7f);
    return 0.5f * __logf((1.f + x) / (1.f - x));
}

__device__ __forceinline__ float warp_sum(float v) {
#pragma unroll
    for (int o = 16; o; o >>= 1) v += __shfl_xor_sync(0xffffffffu, v, o);
    return v;
}

__device__ __forceinline__ float dot4(float4 a, float4 b) {
    return a.x * b.x + a.y * b.y + a.z * b.z + a.w * b.w;
}

// ---------------- K1: MX = X @ W^T (f32x2, K-split 2) -------------------------
__global__ __launch_bounds__(256) void gemm_kernel(
    const float* __restrict__ qin, const float* __restrict__ Wq,
    const float* __restrict__ Wk,  const float* __restrict__ Wv)
{
    __shared__ __align__(16) float Xs[16][64];
    __shared__ __align__(16) float Ws[16][64];

    int bx = blockIdx.x, by = blockIdx.y, ks = blockIdx.z;
    int t  = threadIdx.x;
    int tx = t & 15, ty = t >> 4;

    int m = bx >> 3;
    const float* W = (m == 0) ? Wq : (m == 1) ? Wk : Wv;
    int ibase = (bx & 7) * 64;

    int lr = t >> 2;           // 0..63
    int lk = (t & 3) * 4;      // 0,4,8,12

    int grow = by * 64 + lr;
    int gb = grow >> 8, gs = grow & 255;
    const float* xptr = qin + (gs * 2 + gb) * 512 + lk;
    const float* wptr = W + (ibase + lr) * 512 + lk;

    ull acc2[4][2];
#pragma unroll
    for (int i = 0; i < 4; i++) { acc2[i][0] = 0ull; acc2[i][1] = 0ull; }

    int k0beg = ks * 256;
    for (int k0 = k0beg; k0 < k0beg + 256; k0 += 16) {
        float4 xv = *(const float4*)(xptr + k0);
        float4 wv = *(const float4*)(wptr + k0);
        Xs[lk + 0][lr] = xv.x; Xs[lk + 1][lr] = xv.y;
        Xs[lk + 2][lr] = xv.z; Xs[lk + 3][lr] = xv.w;
        Ws[lk + 0][lr] = wv.x; Ws[lk + 1][lr] = wv.y;
        Ws[lk + 2][lr] = wv.z; Ws[lk + 3][lr] = wv.w;
        __syncthreads();
#pragma unroll
        for (int kk = 0; kk < 16; kk++) {
            float4 a = *(const float4*)&Xs[kk][ty * 4];
            ulonglong2 bb = *(const ulonglong2*)&Ws[kk][tx * 4];
            ull aii;
            PK2(aii, a.x, a.x);
            FMA2(acc2[0][0], aii, bb.x, acc2[0][0]); FMA2(acc2[0][1], aii, bb.y, acc2[0][1]);
            PK2(aii, a.y, a.y);
            FMA2(acc2[1][0], aii, bb.x, acc2[1][0]); FMA2(acc2[1][1], aii, bb.y, acc2[1][1]);
            PK2(aii, a.z, a.z);
            FMA2(acc2[2][0], aii, bb.x, acc2[2][0]); FMA2(acc2[2][1], aii, bb.y, acc2[2][1]);
            PK2(aii, a.w, a.w);
            FMA2(acc2[3][0], aii, bb.x, acc2[3][0]); FMA2(acc2[3][1], aii, bb.y, acc2[3][1]);
        }
        __syncthreads();
    }

    int row0 = by * 64 + ty * 4;
    int col0 = ibase + tx * 4;
#pragma unroll
    for (int i = 0; i < 4; i++) {
        int row = row0 + i;
        int b = row >> 8, s = row & 255;
        float4 v;
        UPK2(v.x, v.y, acc2[i][0]);
        UPK2(v.z, v.w, acc2[i][1]);
        *(float4*)&g_mx[ks][(((m * 2 + b) * 256 + s) * 512) + col0] = v;
    }
}

// ---------------- K2: manifold linear + logmap0 + chunk expmap0 ---------------
// warp-per-row: grid (64, 3), 256 threads. Lane l owns elems l*4+128j, j=0..3.
__global__ __launch_bounds__(256) void postproc_kernel(
    const float* __restrict__ qin, const float* __restrict__ bq,
    const float* __restrict__ bk,  const float* __restrict__ bv)
{
    int t = threadIdx.x, w = t >> 5, l = t & 31;
    int r = blockIdx.x * 8 + w;         // 0..511
    int m = blockIdx.y;
    int b = r >> 8, s = r & 255;

    const float* xrow = qin + (s * 2 + b) * 512;
    const float* mxa  = g_mx[0] + ((m * 2 + b) * 256 + s) * 512;
    const float* mxb  = g_mx[1] + ((m * 2 + b) * 256 + s) * 512;
    const float* bias = (m == 0) ? bq : (m == 1) ? bk : bv;

    float4 xv[4], mv[4], bb[4];
#pragma unroll
    for (int j = 0; j < 4; j++) {
        int e = l * 4 + 128 * j;
        xv[j] = *(const float4*)(xrow + e);
        float4 p = *(const float4*)(mxa + e);
        float4 q = *(const float4*)(mxb + e);
        mv[j] = make_float4(p.x + q.x, p.y + q.y, p.z + q.z, p.w + q.w);
        bb[j] = *(const float4*)(bias + e);
    }

    float sx = 0.f, smx = 0.f;
#pragma unroll
    for (int j = 0; j < 4; j++) { sx += dot4(xv[j], xv[j]); smx += dot4(mv[j], mv[j]); }
    sx = warp_sum(sx); smx = warp_sum(smx);

    float xn  = fmaxf(sqrtf(sx),  1e-15f);
    float mxn = fmaxf(sqrtf(smx), 1e-15f);
    float scm = tanhf((mxn / xn) * artanh_pos(xn)) / mxn;

    float xy = 0.f, x2 = 0.f, y2 = 0.f;
    float4 rv[4];
#pragma unroll
    for (int j = 0; j < 4; j++) {
        rv[j] = make_float4(scm * mv[j].x, scm * mv[j].y, scm * mv[j].z, scm * mv[j].w);
        xy += dot4(rv[j], bb[j]); x2 += dot4(rv[j], rv[j]); y2 += dot4(bb[j], bb[j]);
    }
    xy = warp_sum(xy); x2 = warp_sum(x2); y2 = warp_sum(y2);

    float ca = 1.f + 2.f * xy + y2;
    float cb = 1.f - x2;
    float den = fmaxf(1.f + 2.f * xy + x2 * y2, 1e-15f);
    float rd = __fdividef(1.f, den);

    float so = 0.f;
    float4 ov[4];
#pragma unroll
    for (int j = 0; j < 4; j++) {
        ov[j] = make_float4((ca * rv[j].x + cb * bb[j].x) * rd,
                            (ca * rv[j].y + cb * bb[j].y) * rd,
                            (ca * rv[j].z + cb * bb[j].z) * rd,
                            (ca * rv[j].w + cb * bb[j].w) * rd);
        so += dot4(ov[j], ov[j]);
    }
    so = warp_sum(so);
    float n = fmaxf(sqrtf(so), 1e-15f);
    float pf = (n > 0.996f) ? (0.996f / n) : 1.f;   // projx
    n = fminf(n, 0.996f);
    float ls = artanh_pos(n) / n * pf;              // logmap0 over HID (+proj)

    float* Lrow = g_lin + ((m * 2 + b) * 256 + s) * 512;
#pragma unroll
    for (int j = 0; j < 4; j++) {
        float4 uv = make_float4(ls * ov[j].x, ls * ov[j].y, ls * ov[j].z, ls * ov[j].w);
        float cu = dot4(uv, uv);
        cu += __shfl_xor_sync(0xffffffffu, cu, 1);
        cu += __shfl_xor_sync(0xffffffffu, cu, 2);
        cu += __shfl_xor_sync(0xffffffffu, cu, 4);
        cu += __shfl_xor_sync(0xffffffffu, cu, 8);   // sum over 16-lane group
        float cn = fmaxf(sqrtf(cu), 1e-15f);
        float es = tanhf(cn) / cn;                   // chunk expmap0
        float4 lv = make_float4(es * uv.x, es * uv.y, es * uv.z, es * uv.w);
        *(float4*)(Lrow + l * 4 + 128 * j) = lv;
        if ((l & 15) == 0) {
            float st = es * es * cu;
            int c = (l >> 4) + 2 * j;
            int idx = b * NCH_ + s * 8 + c;
            if (m == 0)       g_qn2[idx] = st;
            else if (m == 1)  g_kl2[idx] = st;
            else              g_gamma[idx] = 2.f / fmaxf(1.f - st, 1e-15f);
        }
    }
}

// ---------------- K3: pairwise scores + sigmoid -------------------------------
// grid (32 qtiles of 8, 16 bh), 256 threads; thread = n, K-row in registers.
__global__ __launch_bounds__(256) void scores_kernel(float* __restrict__ pp)
{
    __shared__ __align__(16) float qs[8 * 64];
    __shared__ float q2s[8];

    int qt = blockIdx.x, bh = blockIdx.y;
    int base = bh * 256;
    int qg0 = qt * 8;
    int t = threadIdx.x;

    const float* gql = g_lin;
    const float* gkl = g_lin + B_ * S_ * HID_;

    for (int idx = t; idx < 8 * 64; idx += 256)
        qs[idx] = gql[(base + qg0) * 64 + idx];
    if (t < 8) q2s[t] = g_qn2[base + qg0 + t];

    ull kr2[32];
    {
        const float* krow = gkl + (base + t) * 64;
#pragma unroll
        for (int i = 0; i < 16; i++) {
            ulonglong2 v = *(const ulonglong2*)(krow + i * 4);
            kr2[2 * i]     = v.x;
            kr2[2 * i + 1] = v.y;
        }
    }
    float y2 = g_kl2[base + t];
    __syncthreads();

    float* prow = pp + (size_t)(bh * 256 + qg0) * 256 + t;

    for (int q = 0; q < 8; q++) {
        const ulonglong2* qr2 = (const ulonglong2*)&qs[q * 64];
        float x2 = q2s[q];

        // dot(q, k)
        ull a0 = 0ull, a1 = 0ull, a2 = 0ull, a3 = 0ull;
#pragma unroll
        for (int i = 0; i < 16; i += 2) {
            ulonglong2 qa = qr2[i];
            ulonglong2 qb = qr2[i + 1];
            FMA2(a0, kr2[2 * i],     qa.x, a0);
            FMA2(a1, kr2[2 * i + 1], qa.y, a1);
            FMA2(a2, kr2[2 * i + 2], qb.x, a2);
            FMA2(a3, kr2[2 * i + 3], qb.y, a3);
        }
        float s0, s1, s2, s3, s4, s5, s6, s7;
        UPK2(s0, s1, a0); UPK2(s2, s3, a1); UPK2(s4, s5, a2); UPK2(s6, s7, a3);
        float xy = ((s0 + s1) + (s2 + s3)) + ((s4 + s5) + (s6 + s7));

        float A  = 1.f - 2.f * xy + y2;
        float Bc = 1.f - x2;
        float den = fmaxf(1.f - 2.f * xy + x2 * y2, 1e-15f);
        float den2 = den * den;

        ull nA2, B2;
        PK2(nA2, -A, -A);
        PK2(B2, Bc, Bc);

        // sum 1/num^2 using pairwise combine: 1/a + 1/b = (a+b)/(a*b)
        float t0 = 0.f, t1a = 0.f;
#pragma unroll
        for (int i = 0; i < 16; i++) {
            ulonglong2 qv = qr2[i];
            ull u, num, sq;
            MUL2(u, B2, kr2[2 * i]);
            FMA2(num, nA2, qv.x, u);
            MUL2(sq, num, num);
            float e0, e1; UPK2(e0, e1, sq);
            t0 = fmaf(frcp(e0 * e1), e0 + e1, t0);

            MUL2(u, B2, kr2[2 * i + 1]);
            FMA2(num, nA2, qv.y, u);
            MUL2(sq, num, num);
            float e2, e3; UPK2(e2, e3, sq);
            t1a = fmaf(frcp(e2 * e3), e2 + e3, t1a);
        }
        float tacc = (t0 + t1a) * den2;
        float tt = rsqrtf(tacc);
        float sc = -2.f * artanh_pos(tt);
        sc = fminf(fmaxf(sc, -1e10f), 1e10f);
        float p = __fdividef(1.f, 1.f + __expf(-sc));
        prow[q * 256] = p;
    }
}

// ---------------- K4: gyro-midpoint + mobius_scalar_mul(0.5) ------------------
// grid (16 qtiles of 16, 16 bh), 256 threads: warp = 2 q rows, lane = d-pair.
// gvs stride 68 floats (272B): float4-staging stays 16B-aligned for every row.
#define SMEM4 ((256 * 68 + 256 + 16 * 256) * 4)
__global__ __launch_bounds__(256) void midpoint_kernel(const float* __restrict__ pp)
{
    extern __shared__ __align__(16) float sm[];
    float* gvs  = sm;                        // [256][68] gamma*vl
    float* gm1s = sm + 256 * 68;             // [256] gamma-1
    float* ps   = gm1s + 256;                // [16][256] probs

    int qt = blockIdx.x, bh = blockIdx.y, t = threadIdx.x;
    int base = bh * 256;
    int qg0 = qt * 16;
    const float* gvl = g_lin + 2 * B_ * S_ * HID_;

    for (int idx4 = t; idx4 < 4096; idx4 += 256) {
        int n = idx4 >> 4, dq = (idx4 & 15) * 4;
        float g = g_gamma[base + n];
        float4 v = *(const float4*)&gvl[(base + n) * 64 + dq];
        v.x *= g; v.y *= g; v.z *= g; v.w *= g;
        *(float4*)&gvs[n * 68 + dq] = v;
    }
    gm1s[t] = g_gamma[base + t] - 1.f;
    {
        const float4* src = (const float4*)(pp + (size_t)(bh * 256 + qg0) * 256);
        float4* dst = (float4*)ps;
        for (int i = t; i < 1024; i += 256) dst[i] = src[i];
    }
    __syncthreads();

    int w = t >> 5, l = t & 31;
    const float* p0 = ps + (2 * w) * 256;
    const float* p1 = p0 + 256;

    ull acc0 = 0ull, acc1 = 0ull;
#pragma unroll 8
    for (int nn = 0; nn < 256; nn++) {
        float a = p0[nn], b = p1[nn];         // smem broadcast
        ull av, bv;
        PK2(av, a, a);
        PK2(bv, b, b);
        ull gv = *(const ull*)&gvs[nn * 68 + 2 * l];
        FMA2(acc0, av, gv, acc0);
        FMA2(acc1, bv, gv, acc1);
    }

    // denominators via strided partials
    float dn0 = 0.f, dn1 = 0.f;
#pragma unroll
    for (int j = 0; j < 8; j++) {
        int n = l + 32 * j;
        float gm = gm1s[n];
        dn0 = fmaf(p0[n], gm, dn0);
        dn1 = fmaf(p1[n], gm, dn1);
    }
    dn0 = warp_sum(dn0);
    dn1 = warp_sum(dn1);

#pragma unroll
    for (int qi = 0; qi < 2; qi++) {
        float dn = qi ? dn1 : dn0;
        ull acc = qi ? acc1 : acc0;
        float sg = (dn >= 0.f) ? 1.f : -1.f;
        float dd = sg * fmaxf(fabsf(dn), 1e-10f);
        float y0, y1; UPK2(y0, y1, acc);
        y0 = __fdividef(y0, dd);
        y1 = __fdividef(y1, dd);
        float nn2 = warp_sum(y0 * y0 + y1 * y1);
        float nm = fmaxf(sqrtf(nn2), 1e-15f);
        float scale = tanhf(0.5f * artanh_pos(nm)) / nm;
        float* crow = g_ctx + (size_t)(bh * 256 + qg0 + 2 * w + qi) * 64;
        crow[2 * l]     = scale * y0;
        crow[2 * l + 1] = scale * y1;
    }
}

// ---------------- K5: head logmap0 -> 512 expmap0 -> [S,B,HID] out ------------
__global__ __launch_bounds__(256) void finalize_kernel(float* __restrict__ out)
{
    __shared__ float sh[8];
    int q = blockIdx.x, b = blockIdx.y;
    int t = threadIdx.x, w = t >> 5, l = t & 31;

    const float* crow = g_ctx + ((b * 8 + w) * 256 + q) * 64;
    float c0 = crow[l], c1 = crow[l + 32];

    float cu = warp_sum(c0 * c0 + c1 * c1);
    float cn = fmaxf(sqrtf(cu), 1e-15f);
    float ls = artanh_pos(cn) / cn;
    float u0 = ls * c0, u1 = ls * c1;

    float us = warp_sum(u0 * u0 + u1 * u1);
    if (l == 0) sh[w] = us;
    __syncthreads();
    float tot = 0.f;
#pragma unroll
    for (int i = 0; i < 8; i++) tot += sh[i];
    float tn = fmaxf(sqrtf(tot), 1e-15f);
    float fs = tanhf(tn) / tn;

    float* orow = out + (q * 2 + b) * 512 + w * 64;
    orow[l]      = fs * u0;
    orow[l + 32] = fs * u1;
}

// ---------------- launch ------------------------------------------------------
extern "C" void kernel_launch(void* const* d_in, const int* in_sizes, int n_in,
                              void* d_out, int out_size)
{
    const float* qin = (const float*)d_in[0];
    const float* Wq  = (const float*)d_in[1];
    const float* bq  = (const float*)d_in[2];
    const float* Wk  = (const float*)d_in[3];
    const float* bk  = (const float*)d_in[4];
    const float* Wv  = (const float*)d_in[5];
    const float* bv  = (const float*)d_in[6];
    float* out = (float*)d_out;

    const int ctx_elems  = S_ * B_ * HID_;        // 262144
    const int prob_elems = B_ * NH_ * S_ * S_;    // 1048576

    float* pp;
    if (out_size >= ctx_elems + prob_elems) {
        pp = out + ctx_elems;
    } else {
        void* sym = nullptr;
        cudaGetSymbolAddress(&sym, g_probs);
        pp = (float*)sym;
    }

    cudaFuncSetAttribute(midpoint_kernel, cudaFuncAttributeMaxDynamicSharedMemorySize, SMEM4);

    gemm_kernel<<<dim3(24, 8, 2), 256>>>(qin, Wq, Wk, Wv);
    postproc_kernel<<<dim3(64, 3), 256>>>(qin, bq, bk, bv);
    scores_kernel<<<dim3(32, 16), 256>>>(pp);
    midpoint_kernel<<<dim3(16, 16), 256, SMEM4>>>(pp);
    finalize_kernel<<<dim3(256, 2), 256>>>(out);
}